// round 1
// baseline (speedup 1.0000x reference)
#include <cuda_runtime.h>

#define PI_F 3.14159265358979323846f
#define DEG2RAD (PI_F / 180.0f)

__constant__ int c_check[8] = {0, 3, 8, 20, 26, 32, 36, 39};

// 142 output rows: marker-major, views inner, skipping (m==1, v<18).
//   r in [0,40)    : m=0, v=r
//   r in [40,62)   : m=1, v=r-40+18
//   r in [62,102)  : m=2, v=r-62
//   r in [102,142) : m=3, v=r-102
__global__ __launch_bounds__(160, 1)
void align_kernel(const float* __restrict__ rot_angles,   // [40]
                  const float* __restrict__ mag,          // [40]
                  const float* __restrict__ xyz,          // [4,3]
                  const float* __restrict__ tilt_angles,  // [8]
                  const float* __restrict__ offset,       // [40,2]
                  float* __restrict__ out)                // [142,2]
{
    int r = threadIdx.x;
    if (r >= 142) return;

    int m, v;
    if (r < 40)       { m = 0; v = r; }
    else if (r < 62)  { m = 1; v = r - 40 + 18; }
    else if (r < 102) { m = 2; v = r - 62; }
    else              { m = 3; v = r - 102; }

    // --- tilt angle (degrees) for this view ---
    int idx1 = 0;
    #pragma unroll
    for (int k = 1; k < 8; k++)
        if (c_check[k] <= v) idx1 = k;
    bool exact = (c_check[idx1] == v);

    float tilt_deg;
    if (exact) {
        tilt_deg = tilt_angles[idx1];
    } else if (v == 14) {
        tilt_deg = -15.0f;
    } else {
        // non-exact, v<39 guarantees idx1 < 7
        float t1 = tilt_angles[idx1];
        float t2 = tilt_angles[idx1 + 1];
        float denom = (float)(c_check[idx1 + 1] - c_check[idx1]);
        float frac = (float)(v - c_check[idx1]) / denom;
        tilt_deg = t1 + (t2 - t1) * frac;
    }

    float tilt = tilt_deg * DEG2RAD;
    float rot  = rot_angles[v] * DEG2RAD;

    float sr, cr, st, ct;
    __sincosf(rot, &sr, &cr);   // fast path is fine at ~1e-7 input scale? use precise:
    // note: rot can be ~|25| rad max (5-sigma of 5*N(0,1) in deg -> rad ~0.4), small args.
    sr = sinf(rot); cr = cosf(rot);
    st = sinf(tilt); ct = cosf(tilt);

    float mg = (v == 0) ? 1.0f : mag[v];
    float ox = (v == 0) ? 0.0f : offset[2 * v + 0];
    float oy = (v == 0) ? 0.0f : offset[2 * v + 1];

    // A = mg * R * T = mg * [[cr*ct, -sr, cr*st], [sr*ct, cr, sr*st]]
    float a00 = mg * cr * ct;
    float a01 = -mg * sr;
    float a02 = mg * cr * st;
    float a10 = mg * sr * ct;
    float a11 = mg * cr;
    float a12 = mg * sr * st;

    float x = xyz[3 * m + 0];
    float y = xyz[3 * m + 1];
    float z = xyz[3 * m + 2];

    float u = fmaf(a00, x, fmaf(a01, y, fmaf(a02, z, ox)));
    float w = fmaf(a10, x, fmaf(a11, y, fmaf(a12, z, oy)));

    float2* out2 = (float2*)out;
    out2[r] = make_float2(u, w);
}

extern "C" void kernel_launch(void* const* d_in, const int* in_sizes, int n_in,
                              void* d_out, int out_size)
{
    const float* rot_angles  = (const float*)d_in[0];
    const float* mag         = (const float*)d_in[1];
    const float* xyz         = (const float*)d_in[2];
    const float* tilt_angles = (const float*)d_in[3];
    const float* offset      = (const float*)d_in[4];
    float* out = (float*)d_out;

    align_kernel<<<1, 160>>>(rot_angles, mag, xyz, tilt_angles, offset, out);
}

// round 2
// speedup vs baseline: 1.0881x; 1.0881x over previous
#include <cuda_runtime.h>

#define DEG2RAD 0.017453292519943295f

// ---- compile-time per-view interpolation tables ----
// CHECK_LIST = {0,3,8,20,26,32,36,39}
// tilt_deg(v) = w1[v]*tilt[i1[v]] + w2[v]*tilt[i2[v]] + bias[v]
__constant__ int   c_i1[40] = {
    0,0,0, 1,1,1,1,1, 2,2,2,2,2,2, 2 /*v14 special*/, 2,2,2,2,2,
    3,3,3,3,3,3, 4,4,4,4,4,4, 5,5,5,5, 6,6,6, 7 };
__constant__ int   c_i2[40] = {
    1,1,1, 2,2,2,2,2, 3,3,3,3,3,3, 3, 3,3,3,3,3,
    4,4,4,4,4,4, 5,5,5,5,5,5, 6,6,6,6, 7,7,7, 7 };
__constant__ float c_w1[40] = {
    1.0f, 0.6666666666666667f, 0.33333333333333337f,            // v0..2
    1.0f, 0.8f, 0.6f, 0.4f, 0.19999999999999996f,               // v3..7
    1.0f, 0.9166666666666666f, 0.8333333333333334f,             // v8..10
    0.75f, 0.6666666666666667f, 0.5833333333333333f,            // v11..13
    0.0f,                                                       // v14 special
    0.41666666666666663f, 0.33333333333333337f, 0.25f,          // v15..17
    0.16666666666666663f, 0.08333333333333337f,                 // v18..19
    1.0f, 0.8333333333333334f, 0.6666666666666667f, 0.5f,       // v20..23
    0.33333333333333337f, 0.16666666666666663f,                 // v24..25
    1.0f, 0.8333333333333334f, 0.6666666666666667f, 0.5f,       // v26..29
    0.33333333333333337f, 0.16666666666666663f,                 // v30..31
    1.0f, 0.75f, 0.5f, 0.25f,                                   // v32..35
    1.0f, 0.6666666666666667f, 0.33333333333333337f,            // v36..38
    1.0f };                                                     // v39
__constant__ float c_w2[40] = {
    0.0f, 0.3333333333333333f, 0.6666666666666666f,
    0.0f, 0.2f, 0.4f, 0.6f, 0.8f,
    0.0f, 0.08333333333333333f, 0.16666666666666666f,
    0.25f, 0.3333333333333333f, 0.4166666666666667f,
    0.0f,
    0.5833333333333334f, 0.6666666666666666f, 0.75f,
    0.8333333333333334f, 0.9166666666666666f,
    0.0f, 0.16666666666666666f, 0.3333333333333333f, 0.5f,
    0.6666666666666666f, 0.8333333333333334f,
    0.0f, 0.16666666666666666f, 0.3333333333333333f, 0.5f,
    0.6666666666666666f, 0.8333333333333334f,
    0.0f, 0.25f, 0.5f, 0.75f,
    0.0f, 0.3333333333333333f, 0.6666666666666666f,
    0.0f };
__constant__ float c_bias[40] = {
    0,0,0,0,0,0,0,0,0,0,0,0,0,0, -15.0f,
    0,0,0,0,0,0,0,0,0,0,0,0,0,0,0,0,0,0,0,0,0,0,0,0,0 };

// 142 output rows: marker-major, views inner, skipping (m==1, v<18).
//   r in [0,40)    : m=0, v=r
//   r in [40,62)   : m=1, v=r-22
//   r in [62,102)  : m=2, v=r-62
//   r in [102,142) : m=3, v=r-102
__global__ __launch_bounds__(160, 1)
void align_kernel(const float* __restrict__ rot_angles,   // [40]
                  const float* __restrict__ mag,          // [40]
                  const float* __restrict__ xyz,          // [4,3]
                  const float* __restrict__ tilt_angles,  // [8]
                  const float* __restrict__ offset,       // [40,2]
                  float* __restrict__ out)                // [142,2]
{
    int r = threadIdx.x;
    if (r >= 142) return;

    int m   = (r >= 40) + (r >= 62) + (r >= 102);
    int sub = (m == 0) ? 0 : (m == 1) ? 22 : (m == 2) ? 62 : 102;
    int v   = r - sub;

    // --- issue all independent global loads up front (max MLP) ---
    float rotd = rot_angles[v];
    float mg_raw = mag[v];
    float2 off = ((const float2*)offset)[v];
    float t1 = tilt_angles[c_i1[v]];
    float t2 = tilt_angles[c_i2[v]];
    float x = xyz[3 * m + 0];
    float y = xyz[3 * m + 1];
    float z = xyz[3 * m + 2];

    float tilt_deg = fmaf(c_w1[v], t1, fmaf(c_w2[v], t2, c_bias[v]));
    float tilt = tilt_deg * DEG2RAD;
    float rot  = rotd * DEG2RAD;

    float sr, cr, st, ct;
    __sincosf(rot,  &sr, &cr);
    __sincosf(tilt, &st, &ct);

    float mg = (v == 0) ? 1.0f : mg_raw;
    float ox = (v == 0) ? 0.0f : off.x;
    float oy = (v == 0) ? 0.0f : off.y;

    // A = mg * [[cr*ct, -sr, cr*st], [sr*ct, cr, sr*st]]
    float mcr = mg * cr;
    float msr = mg * sr;
    float u = fmaf(mcr * ct, x, fmaf(-msr, y, fmaf(mcr * st, z, ox)));
    float w = fmaf(msr * ct, x, fmaf( mcr, y, fmaf(msr * st, z, oy)));

    ((float2*)out)[r] = make_float2(u, w);
}

extern "C" void kernel_launch(void* const* d_in, const int* in_sizes, int n_in,
                              void* d_out, int out_size)
{
    const float* rot_angles  = (const float*)d_in[0];
    const float* mag         = (const float*)d_in[1];
    const float* xyz         = (const float*)d_in[2];
    const float* tilt_angles = (const float*)d_in[3];
    const float* offset      = (const float*)d_in[4];
    float* out = (float*)d_out;

    align_kernel<<<1, 160>>>(rot_angles, mag, xyz, tilt_angles, offset, out);
}

// round 3
// speedup vs baseline: 1.0937x; 1.0052x over previous
#include <cuda_runtime.h>

#define DEG2RAD 0.017453292519943295f

// ---- packed per-view interpolation weights {w1, w2} ----
// CHECK_LIST = {0,3,8,20,26,32,36,39}; tilt_deg(v) = w1*t[i1] + w2*t[i2]
// (v==14 handled by a select to -15). i1/i2 computed arithmetically.
__constant__ float2 c_w[40] = {
    {1.0f, 0.0f}, {0.6666666666666667f, 0.3333333333333333f}, {0.33333333333333337f, 0.6666666666666666f},   // v0..2
    {1.0f, 0.0f}, {0.8f, 0.2f}, {0.6f, 0.4f}, {0.4f, 0.6f}, {0.19999999999999996f, 0.8f},                     // v3..7
    {1.0f, 0.0f}, {0.9166666666666666f, 0.08333333333333333f}, {0.8333333333333334f, 0.16666666666666666f},   // v8..10
    {0.75f, 0.25f}, {0.6666666666666667f, 0.3333333333333333f}, {0.5833333333333333f, 0.4166666666666667f},   // v11..13
    {0.0f, 0.0f},                                                                                             // v14 (special)
    {0.41666666666666663f, 0.5833333333333334f}, {0.33333333333333337f, 0.6666666666666666f}, {0.25f, 0.75f}, // v15..17
    {0.16666666666666663f, 0.8333333333333334f}, {0.08333333333333337f, 0.9166666666666666f},                 // v18..19
    {1.0f, 0.0f}, {0.8333333333333334f, 0.16666666666666666f}, {0.6666666666666667f, 0.3333333333333333f},    // v20..22
    {0.5f, 0.5f}, {0.33333333333333337f, 0.6666666666666666f}, {0.16666666666666663f, 0.8333333333333334f},   // v23..25
    {1.0f, 0.0f}, {0.8333333333333334f, 0.16666666666666666f}, {0.6666666666666667f, 0.3333333333333333f},    // v26..28
    {0.5f, 0.5f}, {0.33333333333333337f, 0.6666666666666666f}, {0.16666666666666663f, 0.8333333333333334f},   // v29..31
    {1.0f, 0.0f}, {0.75f, 0.25f}, {0.5f, 0.5f}, {0.25f, 0.75f},                                               // v32..35
    {1.0f, 0.0f}, {0.6666666666666667f, 0.3333333333333333f}, {0.33333333333333337f, 0.6666666666666666f},    // v36..38
    {1.0f, 0.0f} };                                                                                           // v39

// 142 output rows: marker-major, views inner, skipping (m==1, v<18).
__global__ __launch_bounds__(160, 1)
void align_kernel(const float* __restrict__ rot_angles,   // [40]
                  const float* __restrict__ mag,          // [40]
                  const float* __restrict__ xyz,          // [4,3]
                  const float* __restrict__ tilt_angles,  // [8]
                  const float* __restrict__ offset,       // [40,2]
                  float* __restrict__ out)                // [142,2]
{
    int r = threadIdx.x;
    if (r >= 142) return;

    int m   = (r >= 40) + (r >= 62) + (r >= 102);
    int sub = (m == 0) ? 0 : (m == 1) ? 22 : (m == 2) ? 62 : 102;
    int v   = r - sub;

    // arithmetic interval index (no table load on the critical path)
    int i1 = (v >= 3) + (v >= 8) + (v >= 20) + (v >= 26)
           + (v >= 32) + (v >= 36) + (v >= 39);
    int i2 = (i1 < 7) ? i1 + 1 : 7;

    // --- issue all global loads as early as possible ---
    float t1 = tilt_angles[i1];
    float t2 = tilt_angles[i2];
    float rotd = rot_angles[v];
    float mg_raw = mag[v];
    float2 off = ((const float2*)offset)[v];
    float x = xyz[3 * m + 0];
    float y = xyz[3 * m + 1];
    float z = xyz[3 * m + 2];
    float2 w12 = c_w[v];

    float tilt_deg = fmaf(w12.x, t1, w12.y * t2);
    tilt_deg = (v == 14) ? -15.0f : tilt_deg;

    float tilt = tilt_deg * DEG2RAD;
    float rot  = rotd * DEG2RAD;

    float sr, cr, st, ct;
    __sincosf(rot,  &sr, &cr);
    __sincosf(tilt, &st, &ct);

    float mg = (v == 0) ? 1.0f : mg_raw;
    float ox = (v == 0) ? 0.0f : off.x;
    float oy = (v == 0) ? 0.0f : off.y;

    // A = mg * [[cr*ct, -sr, cr*st], [sr*ct, cr, sr*st]]
    float mcr = mg * cr;
    float msr = mg * sr;
    float u = fmaf(mcr * ct, x, fmaf(-msr, y, fmaf(mcr * st, z, ox)));
    float wv = fmaf(msr * ct, x, fmaf( mcr, y, fmaf(msr * st, z, oy)));

    ((float2*)out)[r] = make_float2(u, wv);
}

extern "C" void kernel_launch(void* const* d_in, const int* in_sizes, int n_in,
                              void* d_out, int out_size)
{
    const float* rot_angles  = (const float*)d_in[0];
    const float* mag         = (const float*)d_in[1];
    const float* xyz         = (const float*)d_in[2];
    const float* tilt_angles = (const float*)d_in[3];
    const float* offset      = (const float*)d_in[4];
    float* out = (float*)d_out;

    align_kernel<<<1, 160>>>(rot_angles, mag, xyz, tilt_angles, offset, out);
}